// round 3
// baseline (speedup 1.0000x reference)
#include <cuda_runtime.h>
#include <math.h>
#include <stdint.h>

// Problem constants
#define BB 4
#define NN_ 4096            // H*W
#define CC 512
#define C1 960

// Scratch (device globals: allocation-free rule)
__device__ float g_normc[(size_t)BB * NN_ * CC];
__device__ float g_ncc[(size_t)BB * NN_ * C1];
__device__ float g_ncs[(size_t)BB * NN_ * C1];
__device__ float g_Q[(size_t)BB * NN_ * C1];
__device__ float g_K[(size_t)BB * NN_ * C1];
__device__ float g_V[(size_t)BB * NN_ * CC];
__device__ float g_A[(size_t)BB * NN_ * NN_];

// ---------------------------------------------------------------------------
// Instance norm over spatial dim (per batch, per channel).
// grid: (Cx/64, B), block: 256 (64 channels x 4 spatial groups)
// ---------------------------------------------------------------------------
__global__ __launch_bounds__(256) void inorm_kernel(
    const float* __restrict__ x, float* __restrict__ y, int Cx)
{
    const int c0 = blockIdx.x * 64;
    const int b  = blockIdx.y;
    const int cl = threadIdx.x & 63;
    const int sg = threadIdx.x >> 6;   // 0..3
    const int c  = c0 + cl;

    const float* xb = x + (size_t)b * NN_ * Cx + c;

    float s = 0.f, s2 = 0.f;
    for (int i = sg; i < NN_; i += 4) {
        float v = xb[(size_t)i * Cx];
        s += v; s2 += v * v;
    }

    __shared__ float sh_s[4][64];
    __shared__ float sh_s2[4][64];
    sh_s[sg][cl] = s;
    sh_s2[sg][cl] = s2;
    __syncthreads();

    __shared__ float sh_mean[64];
    __shared__ float sh_rstd[64];
    if (threadIdx.x < 64) {
        float ts = 0.f, ts2 = 0.f;
        #pragma unroll
        for (int g = 0; g < 4; g++) { ts += sh_s[g][threadIdx.x]; ts2 += sh_s2[g][threadIdx.x]; }
        float mean = ts * (1.0f / NN_);
        float var  = ts2 * (1.0f / NN_) - mean * mean;
        sh_mean[threadIdx.x] = mean;
        sh_rstd[threadIdx.x] = rsqrtf(var + 1e-5f);
    }
    __syncthreads();

    const float mean = sh_mean[cl];
    const float rstd = sh_rstd[cl];
    float* yb = y + (size_t)b * NN_ * Cx + c;
    for (int i = sg; i < NN_; i += 4) {
        yb[(size_t)i * Cx] = (xb[(size_t)i * Cx] - mean) * rstd;
    }
}

// ---------------------------------------------------------------------------
// Tiled SGEMM: C[M,N] = A[M,K] @ B + (bias)
// TRANSB=false: B is [K,N] row-major (NN)
// TRANSB=true : B is [N,K] row-major (NT, C = A @ B^T)
// BM=128, BN=64, BK=8, 256 threads, micro-tile 8x4.
// All dims must divide tile sizes (they do for this problem).
// ---------------------------------------------------------------------------
template<bool TRANSB, bool HAS_BIAS>
__global__ __launch_bounds__(256) void sgemm128x64(
    const float* __restrict__ A, const float* __restrict__ B,
    const float* __restrict__ bias, float* __restrict__ C,
    int M, int N, int K,
    long long strideA, long long strideB, long long strideC)
{
    const int b  = blockIdx.z;
    const int m0 = blockIdx.y * 128;
    const int n0 = blockIdx.x * 64;

    const float* Ab = A + (size_t)b * strideA;
    const float* Bb = B + (size_t)b * strideB;
    float*       Cb = C + (size_t)b * strideC;

    __shared__ float As[8][128];
    __shared__ float Bs[8][64];

    const int tid  = threadIdx.x;
    const int aRow = tid >> 1;            // 0..127
    const int aK   = (tid & 1) * 4;       // 0 or 4
    const int ty   = tid >> 4;            // 0..15
    const int tx   = tid & 15;            // 0..15

    // B load indices
    const int bRowT = tid >> 2;           // NT: 0..63
    const int bKT   = (tid & 3) * 2;      // NT: 0,2,4,6
    const int bKn   = tid >> 5;           // NN: 0..7
    const int bColn = (tid & 31) * 2;     // NN: 0..62

    float acc[8][4];
    #pragma unroll
    for (int i = 0; i < 8; i++)
        #pragma unroll
        for (int j = 0; j < 4; j++) acc[i][j] = 0.f;

    for (int k0 = 0; k0 < K; k0 += 8) {
        // A tile -> As transposed
        float4 a4 = *(const float4*)(Ab + (size_t)(m0 + aRow) * K + k0 + aK);
        As[aK + 0][aRow] = a4.x;
        As[aK + 1][aRow] = a4.y;
        As[aK + 2][aRow] = a4.z;
        As[aK + 3][aRow] = a4.w;

        if (TRANSB) {
            float2 b2 = *(const float2*)(Bb + (size_t)(n0 + bRowT) * K + k0 + bKT);
            Bs[bKT + 0][bRowT] = b2.x;
            Bs[bKT + 1][bRowT] = b2.y;
        } else {
            float2 b2 = *(const float2*)(Bb + (size_t)(k0 + bKn) * N + n0 + bColn);
            Bs[bKn][bColn + 0] = b2.x;
            Bs[bKn][bColn + 1] = b2.y;
        }
        __syncthreads();

        #pragma unroll
        for (int k = 0; k < 8; k++) {
            float a[8], bb[4];
            #pragma unroll
            for (int i = 0; i < 8; i++) a[i] = As[k][ty * 8 + i];
            #pragma unroll
            for (int j = 0; j < 4; j++) bb[j] = Bs[k][tx * 4 + j];
            #pragma unroll
            for (int i = 0; i < 8; i++)
                #pragma unroll
                for (int j = 0; j < 4; j++)
                    acc[i][j] = fmaf(a[i], bb[j], acc[i][j]);
        }
        __syncthreads();
    }

    #pragma unroll
    for (int i = 0; i < 8; i++) {
        const int m = m0 + ty * 8 + i;
        #pragma unroll
        for (int j = 0; j < 4; j++) {
            const int n = n0 + tx * 4 + j;
            float v = acc[i][j];
            if (HAS_BIAS) v += bias[n];
            Cb[(size_t)m * N + n] = v;
        }
    }
}

// ---------------------------------------------------------------------------
// Row softmax over 4096 columns. One block (256 threads) per row.
// Single global read pass (values held in registers), single write.
// ---------------------------------------------------------------------------
__global__ __launch_bounds__(256) void softmax_kernel(float* __restrict__ A)
{
    float* p = A + (size_t)blockIdx.x * NN_;
    const int t = threadIdx.x;

    float rv[16];
    float mx = -1e30f;
    #pragma unroll
    for (int j = 0; j < 16; j++) {
        rv[j] = p[t + j * 256];
        mx = fmaxf(mx, rv[j]);
    }

    // block max
    __shared__ float shm[8];
    #pragma unroll
    for (int o = 16; o > 0; o >>= 1) mx = fmaxf(mx, __shfl_xor_sync(0xffffffffu, mx, o));
    if ((t & 31) == 0) shm[t >> 5] = mx;
    __syncthreads();
    if (t < 32) {
        float x = (t < 8) ? shm[t] : -1e30f;
        #pragma unroll
        for (int o = 4; o > 0; o >>= 1) x = fmaxf(x, __shfl_xor_sync(0xffffffffu, x, o));
        if (t == 0) shm[0] = x;
    }
    __syncthreads();
    const float tmax = shm[0];

    float s = 0.f;
    #pragma unroll
    for (int j = 0; j < 16; j++) {
        rv[j] = __expf(rv[j] - tmax);
        s += rv[j];
    }

    // block sum
    __shared__ float shs[8];
    #pragma unroll
    for (int o = 16; o > 0; o >>= 1) s += __shfl_xor_sync(0xffffffffu, s, o);
    if ((t & 31) == 0) shs[t >> 5] = s;
    __syncthreads();
    if (t < 32) {
        float x = (t < 8) ? shs[t] : 0.f;
        #pragma unroll
        for (int o = 4; o > 0; o >>= 1) x += __shfl_xor_sync(0xffffffffu, x, o);
        if (t == 0) shs[0] = x;
    }
    __syncthreads();
    const float inv = 1.0f / shs[0];

    #pragma unroll
    for (int j = 0; j < 16; j++) p[t + j * 256] = rv[j] * inv;
}

// ---------------------------------------------------------------------------
// Fused M = A@V, E2 = A@(V*V), epilogue: out = sqrt(max(E2-M^2,1e-9))*normc + M
// BM=128 (queries), BN=64 (channels), BK=8. grid (CC/64, NN_/128, B).
// ---------------------------------------------------------------------------
__global__ __launch_bounds__(256) void av_kernel(
    const float* __restrict__ A, const float* __restrict__ V,
    const float* __restrict__ normc, float* __restrict__ out)
{
    const int b  = blockIdx.z;
    const int m0 = blockIdx.y * 128;
    const int n0 = blockIdx.x * 64;

    const float* Ab = A + (size_t)b * NN_ * NN_;
    const float* Vb = V + (size_t)b * NN_ * CC;

    __shared__ float As[8][128];
    __shared__ float Bs[8][64];

    const int tid  = threadIdx.x;
    const int aRow = tid >> 1;
    const int aK   = (tid & 1) * 4;
    const int bK   = tid >> 5;
    const int bCol = (tid & 31) * 2;
    const int ty   = tid >> 4;
    const int tx   = tid & 15;

    float accM[8][4], accE[8][4];
    #pragma unroll
    for (int i = 0; i < 8; i++)
        #pragma unroll
        for (int j = 0; j < 4; j++) { accM[i][j] = 0.f; accE[i][j] = 0.f; }

    for (int k0 = 0; k0 < NN_; k0 += 8) {
        float4 a4 = *(const float4*)(Ab + (size_t)(m0 + aRow) * NN_ + k0 + aK);
        As[aK + 0][aRow] = a4.x;
        As[aK + 1][aRow] = a4.y;
        As[aK + 2][aRow] = a4.z;
        As[aK + 3][aRow] = a4.w;

        float2 b2 = *(const float2*)(Vb + (size_t)(k0 + bK) * CC + n0 + bCol);
        Bs[bK][bCol + 0] = b2.x;
        Bs[bK][bCol + 1] = b2.y;
        __syncthreads();

        #pragma unroll
        for (int k = 0; k < 8; k++) {
            float a[8], bb[4], b2v[4];
            #pragma unroll
            for (int i = 0; i < 8; i++) a[i] = As[k][ty * 8 + i];
            #pragma unroll
            for (int j = 0; j < 4; j++) { bb[j] = Bs[k][tx * 4 + j]; b2v[j] = bb[j] * bb[j]; }
            #pragma unroll
            for (int i = 0; i < 8; i++)
                #pragma unroll
                for (int j = 0; j < 4; j++) {
                    accM[i][j] = fmaf(a[i], bb[j],  accM[i][j]);
                    accE[i][j] = fmaf(a[i], b2v[j], accE[i][j]);
                }
        }
        __syncthreads();
    }

    #pragma unroll
    for (int i = 0; i < 8; i++) {
        const int m = m0 + ty * 8 + i;
        #pragma unroll
        for (int j = 0; j < 4; j++) {
            const int c = n0 + tx * 4 + j;
            const size_t idx = ((size_t)b * NN_ + m) * CC + c;
            const float mm = accM[i][j];
            const float e2 = accE[i][j];
            const float s  = sqrtf(fmaxf(e2 - mm * mm, 1e-9f));
            out[idx] = s * normc[idx] + mm;
        }
    }
}

// ---------------------------------------------------------------------------
extern "C" void kernel_launch(void* const* d_in, const int* in_sizes, int n_in,
                              void* d_out, int out_size)
{
    const float* content   = (const float*)d_in[0];
    const float* style     = (const float*)d_in[1];
    const float* comb_cont = (const float*)d_in[2];
    const float* comb_sty  = (const float*)d_in[3];
    const float* Wq        = (const float*)d_in[4];
    const float* bq        = (const float*)d_in[5];
    const float* Wk        = (const float*)d_in[6];
    const float* bk        = (const float*)d_in[7];
    const float* Wv        = (const float*)d_in[8];
    const float* bv        = (const float*)d_in[9];
    float* out = (float*)d_out;

    float *p_normc, *p_ncc, *p_ncs, *p_Q, *p_K, *p_V, *p_A;
    cudaGetSymbolAddress((void**)&p_normc, g_normc);
    cudaGetSymbolAddress((void**)&p_ncc,   g_ncc);
    cudaGetSymbolAddress((void**)&p_ncs,   g_ncs);
    cudaGetSymbolAddress((void**)&p_Q,     g_Q);
    cudaGetSymbolAddress((void**)&p_K,     g_K);
    cudaGetSymbolAddress((void**)&p_V,     g_V);
    cudaGetSymbolAddress((void**)&p_A,     g_A);

    // 1. Instance norms
    inorm_kernel<<<dim3(CC / 64, BB), 256>>>(content,   p_normc, CC);
    inorm_kernel<<<dim3(C1 / 64, BB), 256>>>(comb_cont, p_ncc,   C1);
    inorm_kernel<<<dim3(C1 / 64, BB), 256>>>(comb_sty,  p_ncs,   C1);

    const int Mall = BB * NN_;   // 16384

    // 2. Projections (batch folded into M; weights shared)
    sgemm128x64<false, true><<<dim3(C1 / 64, Mall / 128, 1), 256>>>(
        p_ncc, Wq, bq, p_Q, Mall, C1, C1, 0, 0, 0);
    sgemm128x64<false, true><<<dim3(C1 / 64, Mall / 128, 1), 256>>>(
        p_ncs, Wk, bk, p_K, Mall, C1, C1, 0, 0, 0);
    sgemm128x64<false, true><<<dim3(CC / 64, Mall / 128, 1), 256>>>(
        style, Wv, bv, p_V, Mall, CC, CC, 0, 0, 0);

    // 3. Attention logits: per batch, Q @ K^T   [4096 x 4096]
    sgemm128x64<true, false><<<dim3(NN_ / 64, NN_ / 128, BB), 256>>>(
        p_Q, p_K, nullptr, p_A, NN_, NN_, C1,
        (long long)NN_ * C1, (long long)NN_ * C1, (long long)NN_ * NN_);

    // 4. Row softmax
    softmax_kernel<<<BB * NN_, 256>>>(p_A);

    // 5. Fused A@V, A@V^2 + output epilogue
    av_kernel<<<dim3(CC / 64, NN_ / 128, BB), 256>>>(p_A, p_V, p_normc, out);

    (void)in_sizes; (void)n_in; (void)out_size;
}

// round 12
// speedup vs baseline: 1.7102x; 1.7102x over previous
#include <cuda_runtime.h>
#include <cuda_bf16.h>
#include <math.h>
#include <stdint.h>

// Problem constants
#define BB 4
#define NN_ 4096            // H*W
#define CC 512
#define C1 960

// ---------------------------------------------------------------------------
// Scratch (device globals: allocation-free rule)
// ---------------------------------------------------------------------------
__device__ float g_normc[(size_t)BB * NN_ * CC];
__device__ float g_ncc[(size_t)BB * NN_ * C1];
__device__ float g_ncs[(size_t)BB * NN_ * C1];
__device__ __nv_bfloat16 g_Qh[(size_t)BB * NN_ * C1];
__device__ __nv_bfloat16 g_Ql[(size_t)BB * NN_ * C1];
__device__ __nv_bfloat16 g_Kh[(size_t)BB * NN_ * C1];
__device__ __nv_bfloat16 g_Kl[(size_t)BB * NN_ * C1];
__device__ __nv_bfloat16 g_VTh[(size_t)BB * CC * NN_];  // V transposed [b][c][tok]
__device__ __nv_bfloat16 g_VTl[(size_t)BB * CC * NN_];
__device__ __nv_bfloat16 g_WTh[(size_t)BB * CC * NN_];  // (V*V) transposed
__device__ __nv_bfloat16 g_WTl[(size_t)BB * CC * NN_];
__device__ float g_P[(size_t)BB * NN_ * NN_];           // logits
__device__ __nv_bfloat16 g_Ah[(size_t)BB * NN_ * NN_];  // softmax hi
__device__ __nv_bfloat16 g_Al[(size_t)BB * NN_ * NN_];  // softmax lo

// ---------------------------------------------------------------------------
// PTX helpers (sm_80-era: mma.sync + ldmatrix + cp.async — valid on sm_103)
// ---------------------------------------------------------------------------
__device__ __forceinline__ uint32_t cvta_smem(const void* p) {
    return (uint32_t)__cvta_generic_to_shared(p);
}

#define CPA16(d, s) \
    asm volatile("cp.async.cg.shared.global [%0], [%1], 16;" :: "r"(d), "l"(s))
#define CPA_COMMIT() asm volatile("cp.async.commit_group;" ::: "memory")
#define CPA_WAIT1()  asm volatile("cp.async.wait_group 1;" ::: "memory")
#define CPA_WAIT0()  asm volatile("cp.async.wait_group 0;" ::: "memory")

__device__ __forceinline__ void ldsm4(uint32_t* r, uint32_t addr) {
    asm volatile("ldmatrix.sync.aligned.m8n8.x4.shared.b16 {%0,%1,%2,%3}, [%4];"
                 : "=r"(r[0]), "=r"(r[1]), "=r"(r[2]), "=r"(r[3]) : "r"(addr));
}

__device__ __forceinline__ void mma16816(float* c, const uint32_t* a, const uint32_t* b) {
    asm volatile(
        "mma.sync.aligned.m16n8k16.row.col.f32.bf16.bf16.f32 "
        "{%0,%1,%2,%3}, {%4,%5,%6,%7}, {%8,%9}, {%0,%1,%2,%3};"
        : "+f"(c[0]), "+f"(c[1]), "+f"(c[2]), "+f"(c[3])
        : "r"(a[0]), "r"(a[1]), "r"(a[2]), "r"(a[3]), "r"(b[0]), "r"(b[1]));
}

// smem tile geometry: rows of 32 bf16, padded to 40 bf16 (80 B) for
// conflict-free ldmatrix (80 B = 20 banks/row).
#define ROWB 80
#define T128 (128 * ROWB)   // 10240 B
#define T64  (64 * ROWB)    // 5120 B
#define STAGE_SZ (4 * T128) // logits stage: Qh,Ql,Kh,Kl  (40960 B)
#define AV_STAGE (2 * T128 + 4 * T64) // A h/l + V h/l + W h/l (40960 B)

// ---------------------------------------------------------------------------
// Instance norm over spatial dim (per batch, per channel).
// ---------------------------------------------------------------------------
__global__ __launch_bounds__(256) void inorm_kernel(
    const float* __restrict__ x, float* __restrict__ y, int Cx)
{
    const int c0 = blockIdx.x * 64;
    const int b  = blockIdx.y;
    const int cl = threadIdx.x & 63;
    const int sg = threadIdx.x >> 6;
    const int c  = c0 + cl;

    const float* xb = x + (size_t)b * NN_ * Cx + c;

    float s = 0.f, s2 = 0.f;
    for (int i = sg; i < NN_; i += 4) {
        float v = xb[(size_t)i * Cx];
        s += v; s2 += v * v;
    }

    __shared__ float sh_s[4][64];
    __shared__ float sh_s2[4][64];
    sh_s[sg][cl] = s;
    sh_s2[sg][cl] = s2;
    __syncthreads();

    __shared__ float sh_mean[64];
    __shared__ float sh_rstd[64];
    if (threadIdx.x < 64) {
        float ts = 0.f, ts2 = 0.f;
        #pragma unroll
        for (int g = 0; g < 4; g++) { ts += sh_s[g][threadIdx.x]; ts2 += sh_s2[g][threadIdx.x]; }
        float mean = ts * (1.0f / NN_);
        float var  = ts2 * (1.0f / NN_) - mean * mean;
        sh_mean[threadIdx.x] = mean;
        sh_rstd[threadIdx.x] = rsqrtf(var + 1e-5f);
    }
    __syncthreads();

    const float mean = sh_mean[cl];
    const float rstd = sh_rstd[cl];
    float* yb = y + (size_t)b * NN_ * Cx + c;
    for (int i = sg; i < NN_; i += 4) {
        yb[(size_t)i * Cx] = (xb[(size_t)i * Cx] - mean) * rstd;
    }
}

// ---------------------------------------------------------------------------
// Projection SGEMM (fp32 mainloop) with split-emitting epilogues.
// EPI=1: write hi/lo bf16 at [m, n] (Q/K).
// EPI=2: write transposed V hi/lo and V^2 hi/lo at [b][n][tok] (V).
// ---------------------------------------------------------------------------
template<int EPI>
__global__ __launch_bounds__(256) void proj_kernel(
    const float* __restrict__ A, const float* __restrict__ B,
    const float* __restrict__ bias,
    __nv_bfloat16* __restrict__ o1, __nv_bfloat16* __restrict__ o2,
    __nv_bfloat16* __restrict__ o3, __nv_bfloat16* __restrict__ o4,
    int M, int N, int K)
{
    const int m0 = blockIdx.y * 128;
    const int n0 = blockIdx.x * 64;

    __shared__ float As[8][128];
    __shared__ float Bs[8][64];

    const int tid  = threadIdx.x;
    const int aRow = tid >> 1;
    const int aK   = (tid & 1) * 4;
    const int ty   = tid >> 4;
    const int tx   = tid & 15;
    const int bKn   = tid >> 5;
    const int bColn = (tid & 31) * 2;

    float acc[8][4];
    #pragma unroll
    for (int i = 0; i < 8; i++)
        #pragma unroll
        for (int j = 0; j < 4; j++) acc[i][j] = 0.f;

    for (int k0 = 0; k0 < K; k0 += 8) {
        float4 a4 = *(const float4*)(A + (size_t)(m0 + aRow) * K + k0 + aK);
        As[aK + 0][aRow] = a4.x;
        As[aK + 1][aRow] = a4.y;
        As[aK + 2][aRow] = a4.z;
        As[aK + 3][aRow] = a4.w;

        float2 b2 = *(const float2*)(B + (size_t)(k0 + bKn) * N + n0 + bColn);
        Bs[bKn][bColn + 0] = b2.x;
        Bs[bKn][bColn + 1] = b2.y;
        __syncthreads();

        #pragma unroll
        for (int k = 0; k < 8; k++) {
            float a[8], bb[4];
            #pragma unroll
            for (int i = 0; i < 8; i++) a[i] = As[k][ty * 8 + i];
            #pragma unroll
            for (int j = 0; j < 4; j++) bb[j] = Bs[k][tx * 4 + j];
            #pragma unroll
            for (int i = 0; i < 8; i++)
                #pragma unroll
                for (int j = 0; j < 4; j++)
                    acc[i][j] = fmaf(a[i], bb[j], acc[i][j]);
        }
        __syncthreads();
    }

    #pragma unroll
    for (int i = 0; i < 8; i++) {
        const int m = m0 + ty * 8 + i;
        #pragma unroll
        for (int j = 0; j < 4; j++) {
            const int n = n0 + tx * 4 + j;
            float v = acc[i][j] + bias[n];
            if (EPI == 1) {
                const size_t idx = (size_t)m * N + n;
                __nv_bfloat16 h = __float2bfloat16(v);
                o1[idx] = h;
                o2[idx] = __float2bfloat16(v - __bfloat162float(h));
            } else {
                const int bb_ = m >> 12;           // 4096 rows per batch
                const int t   = m & 4095;
                const size_t base = ((size_t)bb_ * CC + n) * NN_ + t;
                __nv_bfloat16 h = __float2bfloat16(v);
                o1[base] = h;
                o2[base] = __float2bfloat16(v - __bfloat162float(h));
                float v2 = v * v;
                __nv_bfloat16 h2 = __float2bfloat16(v2);
                o3[base] = h2;
                o4[base] = __float2bfloat16(v2 - __bfloat162float(h2));
            }
        }
    }
}

// ---------------------------------------------------------------------------
// Tile loaders: rows x 32 bf16 (64 B = 4x16B chunks per row) into padded smem.
// ---------------------------------------------------------------------------
__device__ __forceinline__ void ld128(uint32_t sdst, const char* g, long long rowbytes)
{
    #pragma unroll
    for (int i = 0; i < 2; i++) {
        int idx = threadIdx.x + i * 256;
        int r = idx >> 2, c = idx & 3;
        CPA16(sdst + r * ROWB + c * 16, g + (long long)r * rowbytes + c * 16);
    }
}
__device__ __forceinline__ void ld64(uint32_t sdst, const char* g, long long rowbytes)
{
    int idx = threadIdx.x;
    int r = idx >> 2, c = idx & 3;
    CPA16(sdst + r * ROWB + c * 16, g + (long long)r * rowbytes + c * 16);
}

// ---------------------------------------------------------------------------
// Logits: P[b] = Q[b] @ K[b]^T.  bf16 split (hi*hi + hi*lo + lo*hi), fp32 acc.
// Block 128x128, BK=32, 8 warps (4x2), warp tile 32x64. Double-buffered.
// grid (32, 32, 4), 256 threads. dyn smem = 2*STAGE_SZ.
// ---------------------------------------------------------------------------
__global__ __launch_bounds__(256) void logits_mma_kernel(
    const __nv_bfloat16* __restrict__ Qh, const __nv_bfloat16* __restrict__ Ql,
    const __nv_bfloat16* __restrict__ Kh, const __nv_bfloat16* __restrict__ Kl,
    float* __restrict__ P)
{
    extern __shared__ __align__(128) char smem[];
    const uint32_t sb = cvta_smem(smem);

    const int tid    = threadIdx.x;
    const int lane   = tid & 31;
    const int wid    = tid >> 5;
    const int warp_m = wid >> 1;   // 0..3
    const int warp_n = wid & 1;    // 0..1
    const int b  = blockIdx.z;
    const int m0 = blockIdx.y * 128;
    const int n0 = blockIdx.x * 128;

    const char* gQh = (const char*)(Qh + ((size_t)b * NN_ + m0) * C1);
    const char* gQl = (const char*)(Ql + ((size_t)b * NN_ + m0) * C1);
    const char* gKh = (const char*)(Kh + ((size_t)b * NN_ + n0) * C1);
    const char* gKl = (const char*)(Kl + ((size_t)b * NN_ + n0) * C1);
    const long long rb = (long long)C1 * 2;

    float acc[2][8][4];
    #pragma unroll
    for (int i = 0; i < 2; i++)
        #pragma unroll
        for (int j = 0; j < 8; j++)
            #pragma unroll
            for (int q = 0; q < 4; q++) acc[i][j][q] = 0.f;

    // ldmatrix address components
    const int arow = warp_m * 32 + (lane & 15);
    const int acol = (lane >> 4) * 16;                      // byte offset within 32B k-half
    const int brow = warp_n * 64 + (lane & 7) + ((lane >> 4) << 3);
    const int bcol = ((lane >> 3) & 1) * 16;

    const int K_IT = C1 / 32;  // 30

    // prefetch stage 0
    {
        uint32_t base = sb;
        ld128(base + 0 * T128, gQh, rb);
        ld128(base + 1 * T128, gQl, rb);
        ld128(base + 2 * T128, gKh, rb);
        ld128(base + 3 * T128, gKl, rb);
        CPA_COMMIT();
    }

    for (int it = 0; it < K_IT; it++) {
        const int s = it & 1;
        if (it + 1 < K_IT) {
            uint32_t base = sb + (s ^ 1) * STAGE_SZ;
            const long long ko = (long long)(it + 1) * 64;   // 32 bf16 = 64 B
            ld128(base + 0 * T128, gQh + ko, rb);
            ld128(base + 1 * T128, gQl + ko, rb);
            ld128(base + 2 * T128, gKh + ko, rb);
            ld128(base + 3 * T128, gKl + ko, rb);
            CPA_COMMIT();
            CPA_WAIT1();
        } else {
            CPA_WAIT0();
        }
        __syncthreads();

        const uint32_t sQh_ = sb + s * STAGE_SZ;
        const uint32_t sQl_ = sQh_ + T128;
        const uint32_t sKh_ = sQh_ + 2 * T128;
        const uint32_t sKl_ = sQh_ + 3 * T128;

        #pragma unroll
        for (int kh = 0; kh < 2; kh++) {
            const int kb = kh * 32;   // byte offset of k-half
            uint32_t ah[2][4], al[2][4];
            ldsm4(ah[0], sQh_ + (uint32_t)(arow)      * ROWB + kb + acol);
            ldsm4(ah[1], sQh_ + (uint32_t)(arow + 16) * ROWB + kb + acol);
            ldsm4(al[0], sQl_ + (uint32_t)(arow)      * ROWB + kb + acol);
            ldsm4(al[1], sQl_ + (uint32_t)(arow + 16) * ROWB + kb + acol);

            uint32_t bh[8][2], bl[8][2];
            #pragma unroll
            for (int nj2 = 0; nj2 < 4; nj2++) {
                uint32_t t[4];
                ldsm4(t, sKh_ + (uint32_t)(brow + nj2 * 16) * ROWB + kb + bcol);
                bh[2*nj2][0] = t[0]; bh[2*nj2][1] = t[1];
                bh[2*nj2+1][0] = t[2]; bh[2*nj2+1][1] = t[3];
                ldsm4(t, sKl_ + (uint32_t)(brow + nj2 * 16) * ROWB + kb + bcol);
                bl[2*nj2][0] = t[0]; bl[2*nj2][1] = t[1];
                bl[2*nj2+1][0] = t[2]; bl[2*nj2+1][1] = t[3];
            }

            #pragma unroll
            for (int mi = 0; mi < 2; mi++)
                #pragma unroll
                for (int nj = 0; nj < 8; nj++) {
                    mma16816(acc[mi][nj], ah[mi], bh[nj]);
                    mma16816(acc[mi][nj], ah[mi], bl[nj]);
                    mma16816(acc[mi][nj], al[mi], bh[nj]);
                }
        }
        __syncthreads();
    }

    // epilogue
    #pragma unroll
    for (int mi = 0; mi < 2; mi++) {
        const int r0 = m0 + warp_m * 32 + mi * 16 + (lane >> 2);
        #pragma unroll
        for (int nj = 0; nj < 8; nj++) {
            const int col = n0 + warp_n * 64 + nj * 8 + (lane & 3) * 2;
            float* p0 = P + ((size_t)b * NN_ + r0) * NN_ + col;
            p0[0] = acc[mi][nj][0];
            p0[1] = acc[mi][nj][1];
            float* p1 = p0 + (size_t)8 * NN_;
            p1[0] = acc[mi][nj][2];
            p1[1] = acc[mi][nj][3];
        }
    }
}

// ---------------------------------------------------------------------------
// Row softmax (4096 cols) reading fp32 logits, writing bf16 hi/lo split.
// ---------------------------------------------------------------------------
__global__ __launch_bounds__(256) void softmax_kernel(
    const float* __restrict__ P,
    __nv_bfloat16* __restrict__ Ah, __nv_bfloat16* __restrict__ Al)
{
    const float* p = P + (size_t)blockIdx.x * NN_;
    __nv_bfloat16* ph = Ah + (size_t)blockIdx.x * NN_;
    __nv_bfloat16* pl = Al + (size_t)blockIdx.x * NN_;
    const int t = threadIdx.x;

    float rv[16];
    float mx = -1e30f;
    #pragma unroll
    for (int j = 0; j < 16; j++) {
        rv[j] = p[t + j * 256];
        mx = fmaxf(mx, rv[j]);
    }

    __shared__ float shm[8];
    #pragma unroll
    for (int o = 16; o > 0; o >>= 1) mx = fmaxf(mx, __shfl_xor_sync(0xffffffffu, mx, o));
    if ((t & 31) == 0) shm[t >> 5] = mx;
    __syncthreads();
    if (t < 32) {
        float x = (t < 8) ? shm[t] : -1e30f;
        #pragma unroll
        for (int o = 4; o > 0; o >>= 1) x = fmaxf(x, __shfl_xor_sync(0xffffffffu, x, o));
        if (t == 0) shm[0] = x;
    }
    __syncthreads();
    const float tmax = shm[0];

    float s = 0.f;
    #pragma unroll
    for (int j = 0; j < 16; j++) {
        rv[j] = __expf(rv[j] - tmax);
        s += rv[j];
    }

    __shared__ float shs[8];
    #pragma unroll
    for (int o = 16; o > 0; o >>= 1) s += __shfl_xor_sync(0xffffffffu, s, o);
    if ((t & 31) == 0) shs[t >> 5] = s;
    __syncthreads();
    if (t < 32) {
        float x = (t < 8) ? shs[t] : 0.f;
        #pragma unroll
        for (int o = 4; o > 0; o >>= 1) x += __shfl_xor_sync(0xffffffffu, x, o);
        if (t == 0) shs[0] = x;
    }
    __syncthreads();
    const float inv = 1.0f / shs[0];

    #pragma unroll
    for (int j = 0; j < 16; j++) {
        float v = rv[j] * inv;
        __nv_bfloat16 h = __float2bfloat16(v);
        ph[t + j * 256] = h;
        pl[t + j * 256] = __float2bfloat16(v - __bfloat162float(h));
    }
}

// ---------------------------------------------------------------------------
// AV: M = A@V, E2 = A@(V*V) via mma.sync bf16 split; fused variance epilogue.
// Block 128(queries) x 64(channels), BK=32, 8 warps (4x2), warp tile 32x32.
// grid (CC/64=8, 32, 4). Double-buffered. dyn smem = 2*AV_STAGE.
// ---------------------------------------------------------------------------
__global__ __launch_bounds__(256) void av_mma_kernel(
    const __nv_bfloat16* __restrict__ Ah, const __nv_bfloat16* __restrict__ Al,
    const __nv_bfloat16* __restrict__ VTh, const __nv_bfloat16* __restrict__ VTl,
    const __nv_bfloat16* __restrict__ WTh, const __nv_bfloat16* __restrict__ WTl,
    const float* __restrict__ normc, float* __restrict__ out)
{
    extern __shared__ __align__(128) char smem[];
    const uint32_t sb = cvta_smem(smem);

    const int tid    = threadIdx.x;
    const int lane   = tid & 31;
    const int wid    = tid >> 5;
    const int warp_m = wid >> 1;   // 0..3
    const int warp_n = wid & 1;    // 0..1
    const int b  = blockIdx.z;
    const int m0 = blockIdx.y * 128;   // query tile
    const int n0 = blockIdx.x * 64;    // channel tile

    const char* gAh = (const char*)(Ah  + ((size_t)b * NN_ + m0) * NN_);
    const char* gAl = (const char*)(Al  + ((size_t)b * NN_ + m0) * NN_);
    const char* gVh = (const char*)(VTh + ((size_t)b * CC  + n0) * NN_);
    const char* gVl = (const char*)(VTl + ((size_t)b * CC  + n0) * NN_);
    const char* gWh = (const char*)(WTh + ((size_t)b * CC  + n0) * NN_);
    const char* gWl = (const char*)(WTl + ((size_t)b * CC  + n0) * NN_);
    const long long rb = (long long)NN_ * 2;

    float accM[2][4][4], accE[2][4][4];
    #pragma unroll
    for (int i = 0; i < 2; i++)
        #pragma unroll
        for (int j = 0; j < 4; j++)
            #pragma unroll
            for (int q = 0; q < 4; q++) { accM[i][j][q] = 0.f; accE[i][j][q] = 0.f; }

    const int arow = warp_m * 32 + (lane & 15);
    const int acol = (lane >> 4) * 16;
    const int brow = warp_n * 32 + (lane & 7) + ((lane >> 4) << 3);
    const int bcol = ((lane >> 3) & 1) * 16;

    const int K_IT = NN_ / 32;  // 128

    // stage offsets
    const uint32_t oAh = 0, oAl = T128, oVh = 2 * T128, oVl = 2 * T128 + T64;
    const uint32_t oWh = 2 * T128 + 2 * T64, oWl = 2 * T128 + 3 * T64;

    {
        uint32_t base = sb;
        ld128(base + oAh, gAh, rb);
        ld128(base + oAl, gAl, rb);
        ld64(base + oVh, gVh, rb);
        ld64(base + oVl, gVl, rb);
        ld64(base + oWh, gWh, rb);
        ld64(base + oWl, gWl, rb);
        CPA_COMMIT();
    }

    for (int it = 0; it < K_IT; it++) {
        const int s = it & 1;
        if (it + 1 < K_IT) {
            uint32_t base = sb + (s ^ 1) * AV_STAGE;
            const long long ko = (long long)(it + 1) * 64;
            ld128(base + oAh, gAh + ko, rb);
            ld128(base + oAl, gAl + ko, rb);
            ld64(base + oVh, gVh + ko, rb);
            ld64(base + oVl, gVl + ko, rb);
            ld64(base + oWh, gWh + ko, rb);
            ld64(base + oWl, gWl + ko, rb);
            CPA_COMMIT();
            CPA_WAIT1();
        } else {
            CPA_WAIT0();
        }
        __syncthreads();

        const uint32_t st = sb + s * AV_STAGE;

        #pragma unroll
        for (int kh = 0; kh < 2; kh++) {
            const int kb = kh * 32;
            uint32_t ah[2][4], al[2][4];
            ldsm4(ah[0], st + oAh + (uint32_t)(arow)      * ROWB + kb + acol);
            ldsm4(ah[1], st + oAh + (uint32_t)(arow + 16) * ROWB + kb + acol);
            ldsm4(al[0], st + oAl + (uint32_t)(arow)      * ROWB + kb + acol);
            ldsm4(al[1], st + oAl + (uint32_t)(arow + 16) * ROWB + kb + acol);

            uint32_t vh[4][2], vl[4][2], wh[4][2], wl[4][2];
            #pragma unroll
            for (int nj2 = 0; nj2 < 2; nj2++) {
                uint32_t t[4];
                ldsm4(t, st + oVh + (uint32_t)(brow + nj2 * 16) * ROWB + kb + bcol);
                vh[2*nj2][0] = t[0]; vh[2*nj2][1] = t[1];
                vh[2*nj2+1][0] = t[2]; vh[2*nj2+1][1] = t[3];
                ldsm4(t, st + oVl + (uint32_t)(brow + nj2 * 16) * ROWB + kb + bcol);
                vl[2*nj2][0] = t[0]; vl[2*nj2][1] = t[1];
                vl[2*nj2+1][0] = t[2]; vl[2*nj2+1][1] = t[3];
                ldsm4(t, st + oWh + (uint32_t)(brow + nj2 * 16) * ROWB + kb + bcol);
                wh[2*nj2][0] = t[0]; wh[2*nj2][1] = t[1];
                wh[2*nj2+1][0] = t[2]; wh[2*nj2+1][1] = t[3];
                ldsm4(t, st + oWl + (uint32_t)(brow + nj2 * 16) * ROWB + kb + bcol);
                wl[2*nj2][0] = t[0]; wl[2*nj2][1] = t[1];
                wl[2*nj2+1][0] = t[2]; wl[2*nj2+1][1] = t[3];
            }

            #pragma unroll
            for (int mi = 0; mi < 2; mi++)
                #pragma unroll
                for (int nj = 0; nj < 4; nj++) {
                    mma16816(accM[mi][nj], ah[mi], vh[nj]);
                    mma16816(accM[mi][nj], ah[mi], vl[nj]);
                    mma16816(accM[mi][nj], al[mi], vh[nj]);
                    mma16816(accE[mi][nj], ah[mi], wh[nj]);
                    mma16816(accE[mi][nj], ah[mi], wl[nj]);
                    mma16816(accE[mi][nj], al[mi], wh[nj]);
                }
        }
        __syncthreads();
    }

    // epilogue: out = sqrt(max(E2 - M*M, eps)) * normc + M
    #pragma unroll
    for (int mi = 0; mi < 2; mi++) {
        #pragma unroll
        for (int half = 0; half < 2; half++) {
            const int m = m0 + warp_m * 32 + mi * 16 + (lane >> 2) + half * 8;
            #pragma unroll
            for (int nj = 0; nj < 4; nj++) {
                const int c = n0 + warp_n * 32 + nj * 8 + (lane & 3) * 2;
                const size_t idx = ((size_t)b * NN_ + m) * CC + c;
                #pragma unroll
                for (int q = 0; q < 2; q++) {
                    const float mm = accM[mi][nj][half * 2 + q];
                    const float e2 = accE[mi][nj][half * 2 + q];
                    const float sd = sqrtf(fmaxf(e2 - mm * mm, 1e-9f));
                    out[idx + q] = sd * g_normc[idx + q] + mm;
                }
            }
        }
    }
    (void)normc;
}

// ---------------------------------------------------------------------------
extern "C" void kernel_launch(void* const* d_in, const int* in_sizes, int n_in,
                              void* d_out, int out_size)
{
    const float* content   = (const float*)d_in[0];
    const float* style     = (const float*)d_in[1];
    const float* comb_cont = (const float*)d_in[2];
    const float* comb_sty  = (const float*)d_in[3];
    const float* Wq        = (const float*)d_in[4];
    const float* bq        = (const float*)d_in[5];
    const float* Wk        = (const float*)d_in[6];
    const float* bk        = (const float*)d_in[7];
    const float* Wv        = (const float*)d_in[8];
    const float* bv        = (const float*)d_in[9];
    float* out = (float*)d_out;

    float *p_normc, *p_ncc, *p_ncs, *p_P;
    __nv_bfloat16 *p_Qh, *p_Ql, *p_Kh, *p_Kl, *p_VTh, *p_VTl, *p_WTh, *p_WTl, *p_Ah, *p_Al;
    cudaGetSymbolAddress((void**)&p_normc, g_normc);
    cudaGetSymbolAddress((void**)&p_ncc,   g_ncc);
    cudaGetSymbolAddress((void**)&p_ncs,   g_ncs);
    cudaGetSymbolAddress((void**)&p_Qh,    g_Qh);
    cudaGetSymbolAddress((void**)&p_Ql,    g_Ql);
    cudaGetSymbolAddress((void**)&p_Kh,    g_Kh);
    cudaGetSymbolAddress((void**)&p_Kl,    g_Kl);
    cudaGetSymbolAddress((void**)&p_VTh,   g_VTh);
    cudaGetSymbolAddress((void**)&p_VTl,   g_VTl);
    cudaGetSymbolAddress((void**)&p_WTh,   g_WTh);
    cudaGetSymbolAddress((void**)&p_WTl,   g_WTl);
    cudaGetSymbolAddress((void**)&p_P,     g_P);
    cudaGetSymbolAddress((void**)&p_Ah,    g_Ah);
    cudaGetSymbolAddress((void**)&p_Al,    g_Al);

    cudaFuncSetAttribute(logits_mma_kernel, cudaFuncAttributeMaxDynamicSharedMemorySize, 2 * STAGE_SZ);
    cudaFuncSetAttribute(av_mma_kernel,     cudaFuncAttributeMaxDynamicSharedMemorySize, 2 * AV_STAGE);

    // 1. Instance norms
    inorm_kernel<<<dim3(CC / 64, BB), 256>>>(content,   p_normc, CC);
    inorm_kernel<<<dim3(C1 / 64, BB), 256>>>(comb_cont, p_ncc,   C1);
    inorm_kernel<<<dim3(C1 / 64, BB), 256>>>(comb_sty,  p_ncs,   C1);

    const int Mall = BB * NN_;   // 16384

    // 2. Projections with split epilogues
    proj_kernel<1><<<dim3(C1 / 64, Mall / 128), 256>>>(
        p_ncc, Wq, bq, p_Qh, p_Ql, nullptr, nullptr, Mall, C1, C1);
    proj_kernel<1><<<dim3(C1 / 64, Mall / 128), 256>>>(
        p_ncs, Wk, bk, p_Kh, p_Kl, nullptr, nullptr, Mall, C1, C1);
    proj_kernel<2><<<dim3(CC / 64, Mall / 128), 256>>>(
        style, Wv, bv, p_VTh, p_VTl, p_WTh, p_WTl, Mall, CC, CC);

    // 3. Attention logits via mma.sync bf16 split
    logits_mma_kernel<<<dim3(NN_ / 128, NN_ / 128, BB), 256, 2 * STAGE_SZ>>>(
        p_Qh, p_Ql, p_Kh, p_Kl, p_P);

    // 4. Softmax -> bf16 hi/lo
    softmax_kernel<<<BB * NN_, 256>>>(p_P, p_Ah, p_Al);

    // 5. Fused A@V, A@V^2 via mma.sync + variance epilogue
    av_mma_kernel<<<dim3(CC / 64, NN_ / 128, BB), 256, 2 * AV_STAGE>>>(
        p_Ah, p_Al, p_VTh, p_VTl, p_WTh, p_WTl, p_normc, out);

    (void)in_sizes; (void)n_in; (void)out_size;
}